// round 8
// baseline (speedup 1.0000x reference)
#include <cuda_runtime.h>
#include <cuda_fp16.h>
#include <cstdint>

#define NMAX 200000
#define PCAP 65536
#define LDS_A 24   // 16 K-elems + 8 pad -> conflict-free frag LDS

// ---------------- device scratch (BSS: zero at module load) ----------------
__device__ __half g_h1[(size_t)NMAX * 256];
__device__ float  g_acc[(size_t)NMAX * 256];   // invariant: zero outside active window
__device__ __half g_w2t[9 * 256 * 256];        // W2^T fp16 [k][cout][cin]
__device__ int  g_src[9][PCAP];
__device__ int  g_dst[9][PCAP];
__device__ int  g_cnt[9];
__device__ float g_counts[8];
__device__ unsigned char g_flag[NMAX];

// ---------------- prep ----------------
__global__ void prep_kernel(float* out) {
    int t = blockIdx.x * blockDim.x + threadIdx.x;
    if (t < 2048) out[t] = 0.f;
    if (t < 9) g_cnt[t] = 0;
    if (t < 8) g_counts[t] = 0.f;
}

// ---------------- W2 transpose -> fp16 ----------------
__global__ void convw2_kernel(const float* __restrict__ W2) {
    int e = blockIdx.x * blockDim.x + threadIdx.x;
    if (e < 9 * 256 * 256) {
        int k = e >> 16, co = (e >> 8) & 255, ci = e & 255;
        g_w2t[e] = __float2half_rn(W2[(k << 16) + (ci << 8) + co]);
    }
}

// ---------------- layer 1: warp per point ----------------
__global__ void layer1_kernel(const float* __restrict__ feats,
                              const float* __restrict__ W1,
                              const int* __restrict__ nbr, int n) {
    int gw = (blockIdx.x * blockDim.x + threadIdx.x) >> 5;
    int lane = threadIdx.x & 31;
    int nw = (gridDim.x * blockDim.x) >> 5;
    for (int i = gw; i < n; i += nw) {
        int j = -1; float f0 = 0.f, f1 = 0.f, f2 = 0.f;
        if (lane < 9) {
            j = nbr[(size_t)i * 9 + lane];
            if (j >= 0) {
                f0 = feats[(size_t)j * 3 + 0];
                f1 = feats[(size_t)j * 3 + 1];
                f2 = feats[(size_t)j * 3 + 2];
            }
        }
        unsigned vm = __ballot_sync(0xffffffffu, lane < 9 && j >= 0);
        if (lane < 9 && j >= 0 && lane != 4) {
            int pos = atomicAdd(&g_cnt[lane], 1);
            if (pos < PCAP) { g_src[lane][pos] = j; g_dst[lane][pos] = i; }
        }
        if (lane == 0) g_flag[i] = (vm & 0x1EFu) ? 1 : 0;
        float acc[8];
        #pragma unroll
        for (int q = 0; q < 8; q++) acc[q] = 0.f;
        int c0 = lane * 8;
        #pragma unroll
        for (int k = 0; k < 9; k++) {
            if (vm & (1u << k)) {
                float a0 = __shfl_sync(0xffffffffu, f0, k);
                float a1 = __shfl_sync(0xffffffffu, f1, k);
                float a2 = __shfl_sync(0xffffffffu, f2, k);
                const float4* w0 = (const float4*)(W1 + (k * 3 + 0) * 256 + c0);
                const float4* w1 = (const float4*)(W1 + (k * 3 + 1) * 256 + c0);
                const float4* w2 = (const float4*)(W1 + (k * 3 + 2) * 256 + c0);
                float4 x0 = w0[0], x1 = w0[1];
                float4 y0 = w1[0], y1 = w1[1];
                float4 z0 = w2[0], z1 = w2[1];
                acc[0] += a0 * x0.x + a1 * y0.x + a2 * z0.x;
                acc[1] += a0 * x0.y + a1 * y0.y + a2 * z0.y;
                acc[2] += a0 * x0.z + a1 * y0.z + a2 * z0.z;
                acc[3] += a0 * x0.w + a1 * y0.w + a2 * z0.w;
                acc[4] += a0 * x1.x + a1 * y1.x + a2 * z1.x;
                acc[5] += a0 * x1.y + a1 * y1.y + a2 * z1.y;
                acc[6] += a0 * x1.z + a1 * y1.z + a2 * z1.z;
                acc[7] += a0 * x1.w + a1 * y1.w + a2 * z1.w;
            }
        }
        __half2 o[4];
        #pragma unroll
        for (int q = 0; q < 4; q++) {
            float u = acc[2 * q],     v = acc[2 * q + 1];
            o[q] = __floats2half2_rn(u > 0.f ? u : 0.f, v > 0.f ? v : 0.f);
        }
        *(uint4*)(g_h1 + (size_t)i * 256 + c0) = *(uint4*)o;
    }
}

// ---------------- GEMM: fp16, 128x128 tile, cp.async double-buffer --------
__device__ __forceinline__ void mma16816(float c[4], const uint32_t a[4],
                                         const uint32_t b[2]) {
    asm volatile(
        "mma.sync.aligned.m16n8k16.row.col.f32.f16.f16.f32 "
        "{%0,%1,%2,%3}, {%4,%5,%6,%7}, {%8,%9}, {%0,%1,%2,%3};\n"
        : "+f"(c[0]), "+f"(c[1]), "+f"(c[2]), "+f"(c[3])
        : "r"(a[0]), "r"(a[1]), "r"(a[2]), "r"(a[3]), "r"(b[0]), "r"(b[1]));
}
__device__ __forceinline__ void red_v2(float* p, float v0, float v1) {
    asm volatile("red.global.add.v2.f32 [%0], {%1,%2};"
                 :: "l"(p), "f"(v0), "f"(v1) : "memory");
}
__device__ __forceinline__ void cp16(uint32_t saddr, const void* g, bool valid) {
    int sz = valid ? 16 : 0;
    asm volatile("cp.async.cg.shared.global [%0], [%1], 16, %2;"
                 :: "r"(saddr), "l"(g), "r"(sz));
}

#define STAGE_BYTES 12288   // A(6144) + B(6144)
#define SMEM_TOTAL  34816   // >= max(2*STAGE_BYTES, 128*66*4) + 512

__global__ __launch_bounds__(256, 2) void gemm_kernel(int n, int self,
                                                      const int* __restrict__ bids,
                                                      float* __restrict__ out) {
    __shared__ __align__(16) char s_raw[SMEM_TOTAL];
    int tid = threadIdx.x, lane = tid & 31, warp = tid >> 5;
    int wm = warp >> 2, wn = warp & 3;   // 2 x 4 warps -> warp tile 64M x 32N
    int g = lane >> 2, t = lane & 3;

    int kk, tiles, cnt = 0, nhalf, tile0, tstep;
    const int* srcl = nullptr; const int* dstl = nullptr;
    if (self) {
        kk = 4; nhalf = blockIdx.x;          // x fastest: halves of a tile adjacent -> L2 reuse
        tiles = (n + 127) >> 7;
        tile0 = blockIdx.y; tstep = gridDim.y;
    } else {
        int y = blockIdx.y;
        int tap = y >> 1; nhalf = y & 1;
        kk = (tap < 4) ? tap : tap + 1;
        cnt = g_cnt[kk]; if (cnt > PCAP) cnt = PCAP;
        tiles = (cnt + 127) >> 7;
        srcl = g_src[kk]; dstl = g_dst[kk];
        tile0 = blockIdx.x; tstep = gridDim.x;
    }
    const __half* BW = g_w2t + (size_t)kk * 65536 + (size_t)nhalf * 128 * 256;

    uint32_t sbase = (uint32_t)__cvta_generic_to_shared(s_raw);
    int r_ld = tid >> 1, q_ld = tid & 1;

    for (int tile = tile0; tile < tiles; tile += tstep) {
        float acc[4][4][4];
        #pragma unroll
        for (int a = 0; a < 4; a++)
            #pragma unroll
            for (int b = 0; b < 4; b++)
                #pragma unroll
                for (int d = 0; d < 4; d++) acc[a][b][d] = 0.f;

        int arow = tile * 128 + r_ld;
        const __half* asrc = nullptr;
        bool avalid;
        if (self) {
            avalid = (arow < n);
            if (avalid) asrc = g_h1 + (size_t)arow * 256;
        } else {
            avalid = (arow < cnt);
            if (avalid) asrc = g_h1 + (size_t)srcl[arow] * 256;
        }

        #pragma unroll 1
        for (int c = 0; c < 17; c++) {
            if (c < 16) {
                int kc = c * 16;
                uint32_t sa = sbase + (c & 1) * STAGE_BYTES;
                cp16(sa + (r_ld * LDS_A + q_ld * 8) * 2,
                     asrc + kc + q_ld * 8, avalid);
                cp16(sa + 6144 + (r_ld * LDS_A + q_ld * 8) * 2,
                     BW + r_ld * 256 + kc + q_ld * 8, true);
            }
            asm volatile("cp.async.commit_group;");
            if (c == 0) continue;
            if (c < 16) asm volatile("cp.async.wait_group 1;");
            else        asm volatile("cp.async.wait_group 0;");
            __syncthreads();
            {
                const __half* As = (const __half*)(s_raw + ((c - 1) & 1) * STAGE_BYTES);
                const __half* Bs = As + 3072;
                uint32_t afr[4][4];
                #pragma unroll
                for (int mi = 0; mi < 4; mi++) {
                    const __half* ap = As + (wm * 64 + mi * 16 + g) * LDS_A + 2 * t;
                    afr[mi][0] = *(const uint32_t*)ap;
                    afr[mi][1] = *(const uint32_t*)(ap + 8 * LDS_A);
                    afr[mi][2] = *(const uint32_t*)(ap + 8);
                    afr[mi][3] = *(const uint32_t*)(ap + 8 * LDS_A + 8);
                }
                #pragma unroll
                for (int ni = 0; ni < 4; ni++) {
                    int nrow = wn * 32 + ni * 8 + g;
                    uint32_t bf[2];
                    const __half* bp = Bs + nrow * LDS_A + 2 * t;
                    bf[0] = *(const uint32_t*)bp;
                    bf[1] = *(const uint32_t*)(bp + 8);
                    #pragma unroll
                    for (int mi = 0; mi < 4; mi++)
                        mma16816(acc[mi][ni], afr[mi], bf);
                }
            }
            __syncthreads();
        }

        if (!self) {
            #pragma unroll
            for (int mi = 0; mi < 4; mi++) {
                int r0 = wm * 64 + mi * 16 + g;
                #pragma unroll
                for (int ni = 0; ni < 4; ni++) {
                    int col = nhalf * 128 + wn * 32 + ni * 8 + 2 * t;
                    int ra = tile * 128 + r0, rb = ra + 8;
                    if (ra < cnt)
                        red_v2(g_acc + (size_t)dstl[ra] * 256 + col,
                               acc[mi][ni][0], acc[mi][ni][1]);
                    if (rb < cnt)
                        red_v2(g_acc + (size_t)dstl[rb] * 256 + col,
                               acc[mi][ni][2], acc[mi][ni][3]);
                }
            }
        } else {
            // fused: add sparse acc (flagged rows, then re-zero), relu, pooled reduce
            float* tilebuf = (float*)s_raw;                        // [128][66]
            int*   sbatch  = (int*)(s_raw + SMEM_TOTAL - 512);
            __syncthreads();
            if (tid < 128) {
                int r = tile * 128 + tid;
                sbatch[tid] = (r < n) ? bids[r] : -1;
            }
            #pragma unroll
            for (int h = 0; h < 2; h++) {
                __syncthreads();
                if ((wn >> 1) == h) {
                    #pragma unroll
                    for (int mi = 0; mi < 4; mi++) {
                        int rl0 = wm * 64 + mi * 16 + g;
                        #pragma unroll
                        for (int ni = 0; ni < 4; ni++) {
                            int cl = (wn & 1) * 32 + ni * 8 + 2 * t;   // 0..63
                            int gcol = nhalf * 128 + h * 64 + cl;
                            int ra = tile * 128 + rl0, rb = ra + 8;
                            float v0 = acc[mi][ni][0], v1 = acc[mi][ni][1];
                            float v2 = acc[mi][ni][2], v3 = acc[mi][ni][3];
                            if (ra < n && g_flag[ra]) {
                                float2* p = (float2*)(g_acc + (size_t)ra * 256 + gcol);
                                float2 s = *p;
                                *p = make_float2(0.f, 0.f);   // restore zero-invariant
                                v0 += s.x; v1 += s.y;
                            }
                            if (rb < n && g_flag[rb]) {
                                float2* p = (float2*)(g_acc + (size_t)rb * 256 + gcol);
                                float2 s = *p;
                                *p = make_float2(0.f, 0.f);
                                v2 += s.x; v3 += s.y;
                            }
                            tilebuf[rl0 * 66 + cl] = v0;
                            tilebuf[rl0 * 66 + cl + 1] = v1;
                            tilebuf[(rl0 + 8) * 66 + cl] = v2;
                            tilebuf[(rl0 + 8) * 66 + cl + 1] = v3;
                        }
                    }
                }
                __syncthreads();
                if (tid < 64) {
                    int c = tid;
                    float sum = 0.f; int cur = sbatch[0];
                    #pragma unroll 4
                    for (int r = 0; r < 128; r++) {
                        int b = sbatch[r];
                        if (b != cur) {
                            if (cur >= 0)
                                atomicAdd(&out[cur * 256 + nhalf * 128 + h * 64 + c], sum);
                            sum = 0.f; cur = b;
                        }
                        if (b >= 0) {
                            float v = tilebuf[r * 66 + c];
                            sum += (v > 0.f ? v : 0.f);
                        }
                    }
                    if (cur >= 0)
                        atomicAdd(&out[cur * 256 + nhalf * 128 + h * 64 + c], sum);
                }
            }
            __syncthreads();
        }
    }
}

// ---------------- batch counts + finalize ----------------
__global__ void count_kernel(const int* __restrict__ bids, int n) {
    __shared__ int loc[8];
    if (threadIdx.x < 8) loc[threadIdx.x] = 0;
    __syncthreads();
    for (int i = blockIdx.x * blockDim.x + threadIdx.x; i < n;
         i += gridDim.x * blockDim.x)
        atomicAdd(&loc[bids[i]], 1);
    __syncthreads();
    if (threadIdx.x < 8) atomicAdd(&g_counts[threadIdx.x], (float)loc[threadIdx.x]);
}

__global__ void finalize_kernel(float* out) {
    int e = blockIdx.x * 256 + threadIdx.x;
    if (e < 2048) out[e] = out[e] / g_counts[e >> 8];
}

// ---------------- launch ----------------
extern "C" void kernel_launch(void* const* d_in, const int* in_sizes, int n_in,
                              void* d_out, int out_size) {
    const float* feats = (const float*)d_in[0];
    const float* W1    = (const float*)d_in[1];
    const float* W2    = (const float*)d_in[2];
    const int*   nbr   = (const int*)d_in[3];
    const int*   bids  = (const int*)d_in[4];
    int n = in_sizes[0] / 3;
    float* out = (float*)d_out;

    int tiles = (n + 127) / 128;
    prep_kernel<<<8, 256>>>(out);
    convw2_kernel<<<(9 * 256 * 256 + 255) / 256, 256>>>(W2);
    layer1_kernel<<<2048, 256>>>(feats, W1, nbr, n);
    gemm_kernel<<<dim3(40, 16), 256>>>(n, 0, bids, out);        // 8 taps x 2 N-halves
    gemm_kernel<<<dim3(2, tiles), 256>>>(n, 1, bids, out);      // self + fused pool
    count_kernel<<<128, 256>>>(bids, n);
    finalize_kernel<<<8, 256>>>(out);
}

// round 9
// speedup vs baseline: 1.8509x; 1.8509x over previous
#include <cuda_runtime.h>
#include <cuda_fp16.h>
#include <cstdint>

#define NMAX 200000
#define PCAP 65536
#define LDS_A 24   // 16 K-elems + 8 pad -> conflict-free frag LDS

// ---------------- device scratch ----------------
__device__ __half g_h1[(size_t)NMAX * 256];
__device__ float  g_acc[(size_t)NMAX * 256];   // sparse-tap accumulator (flagged rows)
__device__ __half g_w2t[9 * 256 * 256];        // W2^T fp16 [k][cout][cin]
__device__ int  g_src[9][PCAP];
__device__ int  g_dst[9][PCAP];
__device__ int  g_cnt[9];
__device__ float g_counts[8];
__device__ unsigned char g_flag[NMAX];

// ---------------- prep ----------------
__global__ void prep_kernel(float* out) {
    int t = blockIdx.x * blockDim.x + threadIdx.x;
    int stride = gridDim.x * blockDim.x;
    for (int i = t; i < 2048; i += stride) out[i] = 0.f;
    for (int i = t; i < NMAX / 4; i += stride) ((int*)g_flag)[i] = 0;
    if (t < 9) g_cnt[t] = 0;
    if (t < 8) g_counts[t] = 0.f;
}

// ---------------- W2 transpose -> fp16 (coalesced smem transpose) ---------
__global__ void convw2_kernel(const float* __restrict__ W2) {
    __shared__ float tile[32][33];
    int k = blockIdx.z;
    int ci0 = blockIdx.x * 32, co0 = blockIdx.y * 32;
    int tx = threadIdx.x, ty = threadIdx.y;
    // read W2[k][ci][co]: coalesced along co (tx)
    #pragma unroll
    for (int r = 0; r < 32; r += 8) {
        int ci = ci0 + ty + r;
        tile[ty + r][tx] = W2[(k << 16) + (ci << 8) + co0 + tx];
    }
    __syncthreads();
    // write g_w2t[k][co][ci]: coalesced along ci (tx)
    #pragma unroll
    for (int r = 0; r < 32; r += 8) {
        int co = co0 + ty + r;
        g_w2t[(k << 16) + (co << 8) + ci0 + tx] = __float2half_rn(tile[tx][ty + r]);
    }
}

// ---------------- layer 1: warp per point ----------------
__global__ void layer1_kernel(const float* __restrict__ feats,
                              const float* __restrict__ W1,
                              const int* __restrict__ nbr, int n) {
    int gw = (blockIdx.x * blockDim.x + threadIdx.x) >> 5;
    int lane = threadIdx.x & 31;
    int nw = (gridDim.x * blockDim.x) >> 5;
    for (int i = gw; i < n; i += nw) {
        int j = -1; float f0 = 0.f, f1 = 0.f, f2 = 0.f;
        if (lane < 9) {
            j = nbr[(size_t)i * 9 + lane];
            if (j >= 0) {
                f0 = feats[(size_t)j * 3 + 0];
                f1 = feats[(size_t)j * 3 + 1];
                f2 = feats[(size_t)j * 3 + 2];
            }
        }
        unsigned vm = __ballot_sync(0xffffffffu, lane < 9 && j >= 0);
        if (lane < 9 && j >= 0 && lane != 4) {
            int pos = atomicAdd(&g_cnt[lane], 1);
            if (pos < PCAP) { g_src[lane][pos] = j; g_dst[lane][pos] = i; }
        }
        if (lane == 0) g_flag[i] = (vm & 0x1EFu) ? 1 : 0;
        float acc[8];
        #pragma unroll
        for (int q = 0; q < 8; q++) acc[q] = 0.f;
        int c0 = lane * 8;
        #pragma unroll
        for (int k = 0; k < 9; k++) {
            if (vm & (1u << k)) {
                float a0 = __shfl_sync(0xffffffffu, f0, k);
                float a1 = __shfl_sync(0xffffffffu, f1, k);
                float a2 = __shfl_sync(0xffffffffu, f2, k);
                const float4* w0 = (const float4*)(W1 + (k * 3 + 0) * 256 + c0);
                const float4* w1 = (const float4*)(W1 + (k * 3 + 1) * 256 + c0);
                const float4* w2 = (const float4*)(W1 + (k * 3 + 2) * 256 + c0);
                float4 x0 = w0[0], x1 = w0[1];
                float4 y0 = w1[0], y1 = w1[1];
                float4 z0 = w2[0], z1 = w2[1];
                acc[0] += a0 * x0.x + a1 * y0.x + a2 * z0.x;
                acc[1] += a0 * x0.y + a1 * y0.y + a2 * z0.y;
                acc[2] += a0 * x0.z + a1 * y0.z + a2 * z0.z;
                acc[3] += a0 * x0.w + a1 * y0.w + a2 * z0.w;
                acc[4] += a0 * x1.x + a1 * y1.x + a2 * z1.x;
                acc[5] += a0 * x1.y + a1 * y1.y + a2 * z1.y;
                acc[6] += a0 * x1.z + a1 * y1.z + a2 * z1.z;
                acc[7] += a0 * x1.w + a1 * y1.w + a2 * z1.w;
            }
        }
        __half2 o[4];
        #pragma unroll
        for (int q = 0; q < 4; q++) {
            float u = acc[2 * q],     v = acc[2 * q + 1];
            o[q] = __floats2half2_rn(u > 0.f ? u : 0.f, v > 0.f ? v : 0.f);
        }
        *(uint4*)(g_h1 + (size_t)i * 256 + c0) = *(uint4*)o;
    }
}

// ---------------- zero g_acc rows that will receive sparse adds -----------
__global__ void zero_rows_kernel() {
    int tap = blockIdx.y;
    int kk = (tap < 4) ? tap : tap + 1;
    int cnt = g_cnt[kk]; if (cnt > PCAP) cnt = PCAP;
    float4 z = make_float4(0.f, 0.f, 0.f, 0.f);
    for (int p = blockIdx.x; p < cnt; p += gridDim.x) {
        int row = g_dst[kk][p];
        float4* dst = (float4*)(g_acc + (size_t)row * 256);
        for (int e = threadIdx.x; e < 64; e += blockDim.x) dst[e] = z;
    }
}

// ---------------- GEMM: fp16, 128x128 tile, cp.async double-buffer --------
__device__ __forceinline__ void mma16816(float c[4], const uint32_t a[4],
                                         const uint32_t b[2]) {
    asm volatile(
        "mma.sync.aligned.m16n8k16.row.col.f32.f16.f16.f32 "
        "{%0,%1,%2,%3}, {%4,%5,%6,%7}, {%8,%9}, {%0,%1,%2,%3};\n"
        : "+f"(c[0]), "+f"(c[1]), "+f"(c[2]), "+f"(c[3])
        : "r"(a[0]), "r"(a[1]), "r"(a[2]), "r"(a[3]), "r"(b[0]), "r"(b[1]));
}
__device__ __forceinline__ void red_v2(float* p, float v0, float v1) {
    asm volatile("red.global.add.v2.f32 [%0], {%1,%2};"
                 :: "l"(p), "f"(v0), "f"(v1) : "memory");
}
__device__ __forceinline__ void cp16(uint32_t saddr, const void* g, bool valid) {
    int sz = valid ? 16 : 0;
    asm volatile("cp.async.cg.shared.global [%0], [%1], 16, %2;"
                 :: "r"(saddr), "l"(g), "r"(sz));
}

#define STAGE_BYTES 12288   // A(6144) + B(6144)
#define SMEM_TOTAL  34816   // >= max(2*STAGE_BYTES, 128*66*4) + 512

__global__ __launch_bounds__(256, 2) void gemm_kernel(int n, int self,
                                                      const int* __restrict__ bids,
                                                      float* __restrict__ out) {
    __shared__ __align__(16) char s_raw[SMEM_TOTAL];
    int tid = threadIdx.x, lane = tid & 31, warp = tid >> 5;
    int wm = warp >> 2, wn = warp & 3;   // 2 x 4 warps -> warp tile 64M x 32N
    int g = lane >> 2, t = lane & 3;

    int kk, tiles, cnt = 0, nhalf, tile0, tstep;
    const int* srcl = nullptr; const int* dstl = nullptr;
    if (self) {
        kk = 4; nhalf = blockIdx.x;          // x fastest: halves of a tile adjacent -> L2 reuse
        tiles = (n + 127) >> 7;
        tile0 = blockIdx.y; tstep = gridDim.y;
    } else {
        int y = blockIdx.y;
        int tap = y >> 1; nhalf = y & 1;
        kk = (tap < 4) ? tap : tap + 1;
        cnt = g_cnt[kk]; if (cnt > PCAP) cnt = PCAP;
        tiles = (cnt + 127) >> 7;
        srcl = g_src[kk]; dstl = g_dst[kk];
        tile0 = blockIdx.x; tstep = gridDim.x;
    }
    const __half* BW = g_w2t + (size_t)kk * 65536 + (size_t)nhalf * 128 * 256;

    uint32_t sbase = (uint32_t)__cvta_generic_to_shared(s_raw);
    int r_ld = tid >> 1, q_ld = tid & 1;

    for (int tile = tile0; tile < tiles; tile += tstep) {
        float acc[4][4][4];
        #pragma unroll
        for (int a = 0; a < 4; a++)
            #pragma unroll
            for (int b = 0; b < 4; b++)
                #pragma unroll
                for (int d = 0; d < 4; d++) acc[a][b][d] = 0.f;

        int arow = tile * 128 + r_ld;
        const __half* asrc = nullptr;
        bool avalid;
        if (self) {
            avalid = (arow < n);
            if (avalid) asrc = g_h1 + (size_t)arow * 256;
        } else {
            avalid = (arow < cnt);
            if (avalid) asrc = g_h1 + (size_t)srcl[arow] * 256;
        }

        #pragma unroll 1
        for (int c = 0; c < 17; c++) {
            if (c < 16) {
                int kc = c * 16;
                uint32_t sa = sbase + (c & 1) * STAGE_BYTES;
                cp16(sa + (r_ld * LDS_A + q_ld * 8) * 2,
                     asrc + kc + q_ld * 8, avalid);
                cp16(sa + 6144 + (r_ld * LDS_A + q_ld * 8) * 2,
                     BW + r_ld * 256 + kc + q_ld * 8, true);
            }
            asm volatile("cp.async.commit_group;");
            if (c == 0) continue;
            if (c < 16) asm volatile("cp.async.wait_group 1;");
            else        asm volatile("cp.async.wait_group 0;");
            __syncthreads();
            {
                const __half* As = (const __half*)(s_raw + ((c - 1) & 1) * STAGE_BYTES);
                const __half* Bs = As + 3072;
                uint32_t afr[4][4];
                #pragma unroll
                for (int mi = 0; mi < 4; mi++) {
                    const __half* ap = As + (wm * 64 + mi * 16 + g) * LDS_A + 2 * t;
                    afr[mi][0] = *(const uint32_t*)ap;
                    afr[mi][1] = *(const uint32_t*)(ap + 8 * LDS_A);
                    afr[mi][2] = *(const uint32_t*)(ap + 8);
                    afr[mi][3] = *(const uint32_t*)(ap + 8 * LDS_A + 8);
                }
                #pragma unroll
                for (int ni = 0; ni < 4; ni++) {
                    int nrow = wn * 32 + ni * 8 + g;
                    uint32_t bf[2];
                    const __half* bp = Bs + nrow * LDS_A + 2 * t;
                    bf[0] = *(const uint32_t*)bp;
                    bf[1] = *(const uint32_t*)(bp + 8);
                    #pragma unroll
                    for (int mi = 0; mi < 4; mi++)
                        mma16816(acc[mi][ni], afr[mi], bf);
                }
            }
            __syncthreads();
        }

        if (!self) {
            #pragma unroll
            for (int mi = 0; mi < 4; mi++) {
                int r0 = wm * 64 + mi * 16 + g;
                #pragma unroll
                for (int ni = 0; ni < 4; ni++) {
                    int col = nhalf * 128 + wn * 32 + ni * 8 + 2 * t;
                    int ra = tile * 128 + r0, rb = ra + 8;
                    if (ra < cnt)
                        red_v2(g_acc + (size_t)dstl[ra] * 256 + col,
                               acc[mi][ni][0], acc[mi][ni][1]);
                    if (rb < cnt)
                        red_v2(g_acc + (size_t)dstl[rb] * 256 + col,
                               acc[mi][ni][2], acc[mi][ni][3]);
                }
            }
        } else {
            // fused: add sparse acc (flagged rows), relu, pooled reduce
            float* tilebuf = (float*)s_raw;                        // [128][66]
            int*   sbatch  = (int*)(s_raw + SMEM_TOTAL - 512);
            __syncthreads();
            if (tid < 128) {
                int r = tile * 128 + tid;
                sbatch[tid] = (r < n) ? bids[r] : -1;
            }
            #pragma unroll
            for (int h = 0; h < 2; h++) {
                __syncthreads();
                if ((wn >> 1) == h) {
                    #pragma unroll
                    for (int mi = 0; mi < 4; mi++) {
                        int rl0 = wm * 64 + mi * 16 + g;
                        #pragma unroll
                        for (int ni = 0; ni < 4; ni++) {
                            int cl = (wn & 1) * 32 + ni * 8 + 2 * t;   // 0..63
                            int gcol = nhalf * 128 + h * 64 + cl;
                            int ra = tile * 128 + rl0, rb = ra + 8;
                            float v0 = acc[mi][ni][0], v1 = acc[mi][ni][1];
                            float v2 = acc[mi][ni][2], v3 = acc[mi][ni][3];
                            if (ra < n && g_flag[ra]) {
                                float2 s = *(float2*)(g_acc + (size_t)ra * 256 + gcol);
                                v0 += s.x; v1 += s.y;
                            }
                            if (rb < n && g_flag[rb]) {
                                float2 s = *(float2*)(g_acc + (size_t)rb * 256 + gcol);
                                v2 += s.x; v3 += s.y;
                            }
                            tilebuf[rl0 * 66 + cl] = v0;
                            tilebuf[rl0 * 66 + cl + 1] = v1;
                            tilebuf[(rl0 + 8) * 66 + cl] = v2;
                            tilebuf[(rl0 + 8) * 66 + cl + 1] = v3;
                        }
                    }
                }
                __syncthreads();
                if (tid < 64) {
                    int c = tid;
                    float sum = 0.f; int cur = sbatch[0];
                    #pragma unroll 4
                    for (int r = 0; r < 128; r++) {
                        int b = sbatch[r];
                        if (b != cur) {
                            if (cur >= 0)
                                atomicAdd(&out[cur * 256 + nhalf * 128 + h * 64 + c], sum);
                            sum = 0.f; cur = b;
                        }
                        if (b >= 0) {
                            float v = tilebuf[r * 66 + c];
                            sum += (v > 0.f ? v : 0.f);
                        }
                    }
                    if (cur >= 0)
                        atomicAdd(&out[cur * 256 + nhalf * 128 + h * 64 + c], sum);
                }
            }
            __syncthreads();
        }
    }
}

// ---------------- batch counts + finalize ----------------
__global__ void count_kernel(const int* __restrict__ bids, int n) {
    __shared__ int loc[8];
    if (threadIdx.x < 8) loc[threadIdx.x] = 0;
    __syncthreads();
    for (int i = blockIdx.x * blockDim.x + threadIdx.x; i < n;
         i += gridDim.x * blockDim.x)
        atomicAdd(&loc[bids[i]], 1);
    __syncthreads();
    if (threadIdx.x < 8) atomicAdd(&g_counts[threadIdx.x], (float)loc[threadIdx.x]);
}

__global__ void finalize_kernel(float* out) {
    int e = blockIdx.x * 256 + threadIdx.x;
    if (e < 2048) out[e] = out[e] / g_counts[e >> 8];
}

// ---------------- launch ----------------
extern "C" void kernel_launch(void* const* d_in, const int* in_sizes, int n_in,
                              void* d_out, int out_size) {
    const float* feats = (const float*)d_in[0];
    const float* W1    = (const float*)d_in[1];
    const float* W2    = (const float*)d_in[2];
    const int*   nbr   = (const int*)d_in[3];
    const int*   bids  = (const int*)d_in[4];
    int n = in_sizes[0] / 3;
    float* out = (float*)d_out;

    int tiles = (n + 127) / 128;
    prep_kernel<<<64, 256>>>(out);
    convw2_kernel<<<dim3(8, 8, 9), dim3(32, 8)>>>(W2);
    layer1_kernel<<<2048, 256>>>(feats, W1, nbr, n);
    zero_rows_kernel<<<dim3(256, 8), 64>>>();
    gemm_kernel<<<dim3(40, 16), 256>>>(n, 0, bids, out);        // 8 taps x 2 N-halves
    gemm_kernel<<<dim3(2, tiles), 256>>>(n, 1, bids, out);      // self + fused pool
    count_kernel<<<128, 256>>>(bids, n);
    finalize_kernel<<<8, 256>>>(out);
}

// round 10
// speedup vs baseline: 2.2684x; 1.2255x over previous
#include <cuda_runtime.h>
#include <cuda_fp16.h>
#include <cstdint>

#define NMAX 200000
#define PCAP 65536
#define LDSROW 40            // 32 K-halves + 8 pad (80B rows)
#define STAGE_BYTES 20480    // A 128x40x2 + B 128x40x2
#define SMEM_DYN (3 * STAGE_BYTES + 512)

// ---------------- device scratch ----------------
__device__ __half g_h1[(size_t)NMAX * 256];
__device__ float  g_acc[(size_t)NMAX * 256];
__device__ __half g_w2t[9 * 256 * 256];        // W2^T fp16 [k][cout][cin]
__device__ int  g_src[9][PCAP];
__device__ int  g_dst[9][PCAP];
__device__ int  g_cnt[9];
__device__ float g_counts[8];
__device__ unsigned char g_flag[NMAX];

// ---------------- prep ----------------
__global__ void prep_kernel(float* out) {
    int t = blockIdx.x * blockDim.x + threadIdx.x;
    int stride = gridDim.x * blockDim.x;
    for (int i = t; i < 2048; i += stride) out[i] = 0.f;
    for (int i = t; i < NMAX / 4; i += stride) ((int*)g_flag)[i] = 0;
    if (t < 9) g_cnt[t] = 0;
    if (t < 8) g_counts[t] = 0.f;
}

// ---------------- W2 transpose -> fp16 (coalesced smem transpose) ---------
__global__ void convw2_kernel(const float* __restrict__ W2) {
    __shared__ float tile[32][33];
    int k = blockIdx.z;
    int ci0 = blockIdx.x * 32, co0 = blockIdx.y * 32;
    int tx = threadIdx.x, ty = threadIdx.y;
    #pragma unroll
    for (int r = 0; r < 32; r += 8) {
        int ci = ci0 + ty + r;
        tile[ty + r][tx] = W2[(k << 16) + (ci << 8) + co0 + tx];
    }
    __syncthreads();
    #pragma unroll
    for (int r = 0; r < 32; r += 8) {
        int co = co0 + ty + r;
        g_w2t[(k << 16) + (co << 8) + ci0 + tx] = __float2half_rn(tile[tx][ty + r]);
    }
}

// ---------------- layer 1: warp per point ----------------
__global__ void layer1_kernel(const float* __restrict__ feats,
                              const float* __restrict__ W1,
                              const int* __restrict__ nbr, int n) {
    int gw = (blockIdx.x * blockDim.x + threadIdx.x) >> 5;
    int lane = threadIdx.x & 31;
    int nw = (gridDim.x * blockDim.x) >> 5;
    for (int i = gw; i < n; i += nw) {
        int j = -1; float f0 = 0.f, f1 = 0.f, f2 = 0.f;
        if (lane < 9) {
            j = nbr[(size_t)i * 9 + lane];
            if (j >= 0) {
                f0 = feats[(size_t)j * 3 + 0];
                f1 = feats[(size_t)j * 3 + 1];
                f2 = feats[(size_t)j * 3 + 2];
            }
        }
        unsigned vm = __ballot_sync(0xffffffffu, lane < 9 && j >= 0);
        if (lane < 9 && j >= 0 && lane != 4) {
            int pos = atomicAdd(&g_cnt[lane], 1);
            if (pos < PCAP) { g_src[lane][pos] = j; g_dst[lane][pos] = i; }
        }
        if (lane == 0) g_flag[i] = (vm & 0x1EFu) ? 1 : 0;
        float acc[8];
        #pragma unroll
        for (int q = 0; q < 8; q++) acc[q] = 0.f;
        int c0 = lane * 8;
        #pragma unroll
        for (int k = 0; k < 9; k++) {
            if (vm & (1u << k)) {
                float a0 = __shfl_sync(0xffffffffu, f0, k);
                float a1 = __shfl_sync(0xffffffffu, f1, k);
                float a2 = __shfl_sync(0xffffffffu, f2, k);
                const float4* w0 = (const float4*)(W1 + (k * 3 + 0) * 256 + c0);
                const float4* w1 = (const float4*)(W1 + (k * 3 + 1) * 256 + c0);
                const float4* w2 = (const float4*)(W1 + (k * 3 + 2) * 256 + c0);
                float4 x0 = w0[0], x1 = w0[1];
                float4 y0 = w1[0], y1 = w1[1];
                float4 z0 = w2[0], z1 = w2[1];
                acc[0] += a0 * x0.x + a1 * y0.x + a2 * z0.x;
                acc[1] += a0 * x0.y + a1 * y0.y + a2 * z0.y;
                acc[2] += a0 * x0.z + a1 * y0.z + a2 * z0.z;
                acc[3] += a0 * x0.w + a1 * y0.w + a2 * z0.w;
                acc[4] += a0 * x1.x + a1 * y1.x + a2 * z1.x;
                acc[5] += a0 * x1.y + a1 * y1.y + a2 * z1.y;
                acc[6] += a0 * x1.z + a1 * y1.z + a2 * z1.z;
                acc[7] += a0 * x1.w + a1 * y1.w + a2 * z1.w;
            }
        }
        __half2 o[4];
        #pragma unroll
        for (int q = 0; q < 4; q++) {
            float u = acc[2 * q],     v = acc[2 * q + 1];
            o[q] = __floats2half2_rn(u > 0.f ? u : 0.f, v > 0.f ? v : 0.f);
        }
        *(uint4*)(g_h1 + (size_t)i * 256 + c0) = *(uint4*)o;
    }
}

// ---------------- zero g_acc rows right before the sparse scatter ---------
__global__ void zero_rows_kernel() {
    int tap = blockIdx.y;
    int kk = (tap < 4) ? tap : tap + 1;
    int cnt = g_cnt[kk]; if (cnt > PCAP) cnt = PCAP;
    float4 z = make_float4(0.f, 0.f, 0.f, 0.f);
    for (int p = blockIdx.x; p < cnt; p += gridDim.x) {
        int row = g_dst[kk][p];
        float4* dst = (float4*)(g_acc + (size_t)row * 256);
        for (int e = threadIdx.x; e < 64; e += blockDim.x) dst[e] = z;
    }
}

// ---------------- GEMM helpers ----------------
__device__ __forceinline__ void mma16816(float c[4], const uint32_t a[4],
                                         const uint32_t* b) {
    asm volatile(
        "mma.sync.aligned.m16n8k16.row.col.f32.f16.f16.f32 "
        "{%0,%1,%2,%3}, {%4,%5,%6,%7}, {%8,%9}, {%0,%1,%2,%3};\n"
        : "+f"(c[0]), "+f"(c[1]), "+f"(c[2]), "+f"(c[3])
        : "r"(a[0]), "r"(a[1]), "r"(a[2]), "r"(a[3]), "r"(b[0]), "r"(b[1]));
}
__device__ __forceinline__ void ldmx4(uint32_t* r, uint32_t saddr) {
    asm volatile("ldmatrix.sync.aligned.m8n8.x4.shared.b16 {%0,%1,%2,%3}, [%4];"
                 : "=r"(r[0]), "=r"(r[1]), "=r"(r[2]), "=r"(r[3]) : "r"(saddr));
}
__device__ __forceinline__ void red_v2(float* p, float v0, float v1) {
    asm volatile("red.global.add.v2.f32 [%0], {%1,%2};"
                 :: "l"(p), "f"(v0), "f"(v1) : "memory");
}
__device__ __forceinline__ void cp16(uint32_t saddr, const void* g, bool valid) {
    int sz = valid ? 16 : 0;
    asm volatile("cp.async.cg.shared.global [%0], [%1], 16, %2;"
                 :: "r"(saddr), "l"(g), "r"(sz));
}

// ---------------- unified GEMM: 128M x 128N, KC=32, 3-stage ring, ldmatrix -
__global__ __launch_bounds__(256, 2) void gemm_kernel(int n, int self,
                                                      const int* __restrict__ bids,
                                                      float* __restrict__ out) {
    extern __shared__ __align__(16) char dsm[];
    uint32_t sbase = (uint32_t)__cvta_generic_to_shared(dsm);
    int tid = threadIdx.x, lane = tid & 31, warp = tid >> 5;
    int wm = warp >> 2, wn = warp & 3;    // warp tile 64M x 32N
    int g = lane >> 2, t = lane & 3;

    int kk, tiles, cnt = 0, nhalf, tile0, tstep;
    const int* srcl = nullptr; const int* dstl = nullptr;
    if (self) {
        kk = 4; nhalf = blockIdx.x;       // x fastest -> A tile L2 reuse across halves
        tiles = (n + 127) >> 7;
        tile0 = blockIdx.y; tstep = gridDim.y;
    } else {
        int y = blockIdx.y;
        int tap = y >> 1; nhalf = y & 1;
        kk = (tap < 4) ? tap : tap + 1;
        cnt = g_cnt[kk]; if (cnt > PCAP) cnt = PCAP;
        tiles = (cnt + 127) >> 7;
        srcl = g_src[kk]; dstl = g_dst[kk];
        tile0 = blockIdx.x; tstep = gridDim.x;
    }
    const __half* BW = g_w2t + (size_t)kk * 65536 + (size_t)nhalf * 128 * 256;

    int r0 = tid >> 2, q0 = tid & 3;     // load coords: rows r0, r0+64; 16B slot q0

    for (int tile = tile0; tile < tiles; tile += tstep) {
        float acc[4][4][4];
        #pragma unroll
        for (int a = 0; a < 4; a++)
            #pragma unroll
            for (int b = 0; b < 4; b++)
                #pragma unroll
                for (int d = 0; d < 4; d++) acc[a][b][d] = 0.f;

        const __half* asrc[2]; bool aval[2];
        #pragma unroll
        for (int i = 0; i < 2; i++) {
            int ar = tile * 128 + r0 + i * 64;
            if (self) {
                aval[i] = (ar < n);
                asrc[i] = g_h1 + (size_t)(aval[i] ? ar : 0) * 256;
            } else {
                aval[i] = (ar < cnt);
                asrc[i] = g_h1 + (size_t)(aval[i] ? srcl[ar] : 0) * 256;
            }
        }

        auto issue = [&](int c) {
            if (c < 8) {
                int kc = c * 32;
                uint32_t sa = sbase + (uint32_t)(c % 3) * STAGE_BYTES;
                #pragma unroll
                for (int i = 0; i < 2; i++) {
                    uint32_t da = sa + ((r0 + i * 64) * LDSROW + q0 * 8) * 2;
                    cp16(da, asrc[i] + kc + q0 * 8, aval[i]);
                    cp16(da + 10240, BW + (r0 + i * 64) * 256 + kc + q0 * 8, true);
                }
            }
            asm volatile("cp.async.commit_group;");
        };

        issue(0); issue(1);
        #pragma unroll 1
        for (int c = 0; c < 8; c++) {
            asm volatile("cp.async.wait_group 1;");
            __syncthreads();
            issue(c + 2);
            uint32_t As_u = sbase + (uint32_t)(c % 3) * STAGE_BYTES;
            uint32_t Bs_u = As_u + 10240;
            #pragma unroll
            for (int ks = 0; ks < 32; ks += 16) {
                uint32_t afr[4][4];
                #pragma unroll
                for (int mi = 0; mi < 4; mi++) {
                    int row = wm * 64 + mi * 16 + ((lane >> 3) & 1) * 8 + (lane & 7);
                    int kofs = ks + ((lane >> 4) << 3);
                    ldmx4(afr[mi], As_u + (row * LDSROW + kofs) * 2);
                }
                #pragma unroll
                for (int p = 0; p < 2; p++) {
                    uint32_t bb[4];
                    int row = wn * 32 + p * 16 + ((lane >> 4) << 3) + (lane & 7);
                    int kofs = ks + (((lane >> 3) & 1) << 3);
                    ldmx4(bb, Bs_u + (row * LDSROW + kofs) * 2);
                    #pragma unroll
                    for (int mi = 0; mi < 4; mi++) {
                        mma16816(acc[mi][2 * p],     afr[mi], bb);
                        mma16816(acc[mi][2 * p + 1], afr[mi], bb + 2);
                    }
                }
            }
        }
        __syncthreads();   // pipeline smem free for epilogue reuse

        if (!self) {
            #pragma unroll
            for (int mi = 0; mi < 4; mi++) {
                int rr = wm * 64 + mi * 16 + g;
                #pragma unroll
                for (int ni = 0; ni < 4; ni++) {
                    int col = nhalf * 128 + wn * 32 + ni * 8 + 2 * t;
                    int ra = tile * 128 + rr, rb = ra + 8;
                    if (ra < cnt)
                        red_v2(g_acc + (size_t)dstl[ra] * 256 + col,
                               acc[mi][ni][0], acc[mi][ni][1]);
                    if (rb < cnt)
                        red_v2(g_acc + (size_t)dstl[rb] * 256 + col,
                               acc[mi][ni][2], acc[mi][ni][3]);
                }
            }
        } else {
            // fused: add sparse acc (flagged rows), relu, pooled reduce
            float* tilebuf = (float*)dsm;                         // [128][66]
            int*   sbatch  = (int*)(dsm + 3 * STAGE_BYTES);
            if (tid < 128) {
                int r = tile * 128 + tid;
                sbatch[tid] = (r < n) ? bids[r] : -1;
            }
            #pragma unroll
            for (int h = 0; h < 2; h++) {
                __syncthreads();
                if ((wn >> 1) == h) {
                    #pragma unroll
                    for (int mi = 0; mi < 4; mi++) {
                        int rl0 = wm * 64 + mi * 16 + g;
                        #pragma unroll
                        for (int ni = 0; ni < 4; ni++) {
                            int cl = (wn & 1) * 32 + ni * 8 + 2 * t;   // 0..63
                            int gcol = nhalf * 128 + h * 64 + cl;
                            int ra = tile * 128 + rl0, rb = ra + 8;
                            float v0 = acc[mi][ni][0], v1 = acc[mi][ni][1];
                            float v2 = acc[mi][ni][2], v3 = acc[mi][ni][3];
                            if (ra < n && g_flag[ra]) {
                                float2 s = *(float2*)(g_acc + (size_t)ra * 256 + gcol);
                                v0 += s.x; v1 += s.y;
                            }
                            if (rb < n && g_flag[rb]) {
                                float2 s = *(float2*)(g_acc + (size_t)rb * 256 + gcol);
                                v2 += s.x; v3 += s.y;
                            }
                            tilebuf[rl0 * 66 + cl] = v0;
                            tilebuf[rl0 * 66 + cl + 1] = v1;
                            tilebuf[(rl0 + 8) * 66 + cl] = v2;
                            tilebuf[(rl0 + 8) * 66 + cl + 1] = v3;
                        }
                    }
                }
                __syncthreads();
                {
                    int col = tid & 63, q = tid >> 6;          // 4 row-groups x 64 cols
                    float sum = 0.f; int cur = -1;
                    #pragma unroll 8
                    for (int rr = q * 32; rr < q * 32 + 32; rr++) {
                        int b = sbatch[rr];
                        if (b != cur) {
                            if (cur >= 0)
                                atomicAdd(&out[cur * 256 + nhalf * 128 + h * 64 + col], sum);
                            sum = 0.f; cur = b;
                        }
                        if (b >= 0) {
                            float v = tilebuf[rr * 66 + col];
                            sum += (v > 0.f ? v : 0.f);
                        }
                    }
                    if (cur >= 0)
                        atomicAdd(&out[cur * 256 + nhalf * 128 + h * 64 + col], sum);
                }
            }
            __syncthreads();
        }
    }
}

// ---------------- counts + finalize ----------------
__global__ void count_kernel(const int* __restrict__ bids, int n) {
    __shared__ int loc[8];
    if (threadIdx.x < 8) loc[threadIdx.x] = 0;
    __syncthreads();
    for (int i = blockIdx.x * blockDim.x + threadIdx.x; i < n;
         i += gridDim.x * blockDim.x)
        atomicAdd(&loc[bids[i]], 1);
    __syncthreads();
    if (threadIdx.x < 8) atomicAdd(&g_counts[threadIdx.x], (float)loc[threadIdx.x]);
}

__global__ void finalize_kernel(float* out) {
    int e = blockIdx.x * 256 + threadIdx.x;
    if (e < 2048) out[e] = out[e] / g_counts[e >> 8];
}

// ---------------- launch ----------------
extern "C" void kernel_launch(void* const* d_in, const int* in_sizes, int n_in,
                              void* d_out, int out_size) {
    const float* feats = (const float*)d_in[0];
    const float* W1    = (const float*)d_in[1];
    const float* W2    = (const float*)d_in[2];
    const int*   nbr   = (const int*)d_in[3];
    const int*   bids  = (const int*)d_in[4];
    int n = in_sizes[0] / 3;
    float* out = (float*)d_out;

    static int cfg = 0;
    if (!cfg) {
        cudaFuncSetAttribute(gemm_kernel,
                             cudaFuncAttributeMaxDynamicSharedMemorySize, SMEM_DYN);
        cfg = 1;
    }

    int tiles = (n + 127) / 128;
    prep_kernel<<<64, 256>>>(out);
    convw2_kernel<<<dim3(8, 8, 9), dim3(32, 8)>>>(W2);
    layer1_kernel<<<2048, 256>>>(feats, W1, nbr, n);
    zero_rows_kernel<<<dim3(256, 8), 64>>>();
    gemm_kernel<<<dim3(40, 16), 256, SMEM_DYN>>>(n, 0, bids, out);   // 8 taps x 2 halves
    gemm_kernel<<<dim3(2, tiles), 256, SMEM_DYN>>>(n, 1, bids, out); // self + fused pool
    count_kernel<<<128, 256>>>(bids, n);
    finalize_kernel<<<8, 256>>>(out);
}

// round 11
// speedup vs baseline: 2.3344x; 1.0291x over previous
#include <cuda_runtime.h>
#include <cuda_fp16.h>
#include <cstdint>

#define NMAX 200000
#define PCAP 65536
#define LDSROW 72            // 64 K-halves + 8 pad (144B rows)
#define STAGE_BYTES 36864    // A 128x72x2 + B 128x72x2
#define SMEM_DYN (3 * STAGE_BYTES + 512)

// ---------------- device scratch ----------------
__device__ __half g_h1[(size_t)NMAX * 256];
__device__ float  g_acc[(size_t)NMAX * 256];
__device__ __half g_w2t[9 * 256 * 256];        // W2^T fp16 [k][cout][cin]
__device__ int  g_src[9][PCAP];
__device__ int  g_dst[9][PCAP];
__device__ int  g_cnt[9];
__device__ float g_counts[8];
__device__ unsigned char g_flag[NMAX];

// ---------------- prep ----------------
__global__ void prep_kernel(float* out) {
    int t = blockIdx.x * blockDim.x + threadIdx.x;
    int stride = gridDim.x * blockDim.x;
    for (int i = t; i < 2048; i += stride) out[i] = 0.f;
    for (int i = t; i < NMAX / 4; i += stride) ((int*)g_flag)[i] = 0;
    if (t < 9) g_cnt[t] = 0;
    if (t < 8) g_counts[t] = 0.f;
}

// ---------------- W2 transpose -> fp16 (coalesced smem transpose) ---------
__global__ void convw2_kernel(const float* __restrict__ W2) {
    __shared__ float tile[32][33];
    int k = blockIdx.z;
    int ci0 = blockIdx.x * 32, co0 = blockIdx.y * 32;
    int tx = threadIdx.x, ty = threadIdx.y;
    #pragma unroll
    for (int r = 0; r < 32; r += 8) {
        int ci = ci0 + ty + r;
        tile[ty + r][tx] = W2[(k << 16) + (ci << 8) + co0 + tx];
    }
    __syncthreads();
    #pragma unroll
    for (int r = 0; r < 32; r += 8) {
        int co = co0 + ty + r;
        g_w2t[(k << 16) + (co << 8) + ci0 + tx] = __float2half_rn(tile[tx][ty + r]);
    }
}

// ---------------- layer 1: warp per point ----------------
__global__ void layer1_kernel(const float* __restrict__ feats,
                              const float* __restrict__ W1,
                              const int* __restrict__ nbr, int n) {
    int gw = (blockIdx.x * blockDim.x + threadIdx.x) >> 5;
    int lane = threadIdx.x & 31;
    int nw = (gridDim.x * blockDim.x) >> 5;
    for (int i = gw; i < n; i += nw) {
        int j = -1; float f0 = 0.f, f1 = 0.f, f2 = 0.f;
        if (lane < 9) {
            j = nbr[(size_t)i * 9 + lane];
            if (j >= 0) {
                f0 = feats[(size_t)j * 3 + 0];
                f1 = feats[(size_t)j * 3 + 1];
                f2 = feats[(size_t)j * 3 + 2];
            }
        }
        unsigned vm = __ballot_sync(0xffffffffu, lane < 9 && j >= 0);
        if (lane < 9 && j >= 0 && lane != 4) {
            int pos = atomicAdd(&g_cnt[lane], 1);
            if (pos < PCAP) { g_src[lane][pos] = j; g_dst[lane][pos] = i; }
        }
        if (lane == 0) g_flag[i] = (vm & 0x1EFu) ? 1 : 0;
        float acc[8];
        #pragma unroll
        for (int q = 0; q < 8; q++) acc[q] = 0.f;
        int c0 = lane * 8;
        #pragma unroll
        for (int k = 0; k < 9; k++) {
            if (vm & (1u << k)) {
                float a0 = __shfl_sync(0xffffffffu, f0, k);
                float a1 = __shfl_sync(0xffffffffu, f1, k);
                float a2 = __shfl_sync(0xffffffffu, f2, k);
                const float4* w0 = (const float4*)(W1 + (k * 3 + 0) * 256 + c0);
                const float4* w1 = (const float4*)(W1 + (k * 3 + 1) * 256 + c0);
                const float4* w2 = (const float4*)(W1 + (k * 3 + 2) * 256 + c0);
                float4 x0 = w0[0], x1 = w0[1];
                float4 y0 = w1[0], y1 = w1[1];
                float4 z0 = w2[0], z1 = w2[1];
                acc[0] += a0 * x0.x + a1 * y0.x + a2 * z0.x;
                acc[1] += a0 * x0.y + a1 * y0.y + a2 * z0.y;
                acc[2] += a0 * x0.z + a1 * y0.z + a2 * z0.z;
                acc[3] += a0 * x0.w + a1 * y0.w + a2 * z0.w;
                acc[4] += a0 * x1.x + a1 * y1.x + a2 * z1.x;
                acc[5] += a0 * x1.y + a1 * y1.y + a2 * z1.y;
                acc[6] += a0 * x1.z + a1 * y1.z + a2 * z1.z;
                acc[7] += a0 * x1.w + a1 * y1.w + a2 * z1.w;
            }
        }
        __half2 o[4];
        #pragma unroll
        for (int q = 0; q < 4; q++) {
            float u = acc[2 * q],     v = acc[2 * q + 1];
            o[q] = __floats2half2_rn(u > 0.f ? u : 0.f, v > 0.f ? v : 0.f);
        }
        *(uint4*)(g_h1 + (size_t)i * 256 + c0) = *(uint4*)o;
    }
}

// ---------------- zero g_acc rows right before the sparse scatter ---------
// (placement is load-bearing: keeps zeroed lines L2-hot for the atomics)
__global__ void zero_rows_kernel() {
    int tap = blockIdx.y;
    int kk = (tap < 4) ? tap : tap + 1;
    int cnt = g_cnt[kk]; if (cnt > PCAP) cnt = PCAP;
    float4 z = make_float4(0.f, 0.f, 0.f, 0.f);
    for (int p = blockIdx.x; p < cnt; p += gridDim.x) {
        int row = g_dst[kk][p];
        float4* dst = (float4*)(g_acc + (size_t)row * 256);
        for (int e = threadIdx.x; e < 64; e += blockDim.x) dst[e] = z;
    }
}

// ---------------- GEMM helpers ----------------
__device__ __forceinline__ void mma16816(float c[4], const uint32_t a[4],
                                         const uint32_t* b) {
    asm volatile(
        "mma.sync.aligned.m16n8k16.row.col.f32.f16.f16.f32 "
        "{%0,%1,%2,%3}, {%4,%5,%6,%7}, {%8,%9}, {%0,%1,%2,%3};\n"
        : "+f"(c[0]), "+f"(c[1]), "+f"(c[2]), "+f"(c[3])
        : "r"(a[0]), "r"(a[1]), "r"(a[2]), "r"(a[3]), "r"(b[0]), "r"(b[1]));
}
__device__ __forceinline__ void ldmx4(uint32_t* r, uint32_t saddr) {
    asm volatile("ldmatrix.sync.aligned.m8n8.x4.shared.b16 {%0,%1,%2,%3}, [%4];"
                 : "=r"(r[0]), "=r"(r[1]), "=r"(r[2]), "=r"(r[3]) : "r"(saddr));
}
__device__ __forceinline__ void red_v2(float* p, float v0, float v1) {
    asm volatile("red.global.add.v2.f32 [%0], {%1,%2};"
                 :: "l"(p), "f"(v0), "f"(v1) : "memory");
}
__device__ __forceinline__ void cp16(uint32_t saddr, const void* g, bool valid) {
    int sz = valid ? 16 : 0;
    asm volatile("cp.async.cg.shared.global [%0], [%1], 16, %2;"
                 :: "r"(saddr), "l"(g), "r"(sz));
}

// ---------------- unified GEMM: 128M x 128N, KC=64, 3-stage ring, ldmatrix -
__global__ __launch_bounds__(256, 2) void gemm_kernel(int n, int self,
                                                      const int* __restrict__ bids,
                                                      float* __restrict__ out) {
    extern __shared__ __align__(16) char dsm[];
    uint32_t sbase = (uint32_t)__cvta_generic_to_shared(dsm);
    int tid = threadIdx.x, lane = tid & 31, warp = tid >> 5;
    int wm = warp >> 2, wn = warp & 3;    // warp tile 64M x 32N
    int g = lane >> 2, t = lane & 3;

    int kk, tiles, cnt = 0, nhalf, tile0, tstep;
    const int* srcl = nullptr; const int* dstl = nullptr;
    if (self) {
        kk = 4; nhalf = blockIdx.x;       // x fastest -> A tile L2 reuse across halves
        tiles = (n + 127) >> 7;
        tile0 = blockIdx.y; tstep = gridDim.y;
    } else {
        int y = blockIdx.y;
        int tap = y >> 1; nhalf = y & 1;
        kk = (tap < 4) ? tap : tap + 1;
        cnt = g_cnt[kk]; if (cnt > PCAP) cnt = PCAP;
        tiles = (cnt + 127) >> 7;
        srcl = g_src[kk]; dstl = g_dst[kk];
        tile0 = blockIdx.x; tstep = gridDim.x;
    }
    const __half* BW = g_w2t + (size_t)kk * 65536 + (size_t)nhalf * 128 * 256;

    int r_ld = tid >> 3, q_ld = tid & 7;   // 32 row-band base, 8 x 16B slots/row

    for (int tile = tile0; tile < tiles; tile += tstep) {
        float acc[4][4][4];
        #pragma unroll
        for (int a = 0; a < 4; a++)
            #pragma unroll
            for (int b = 0; b < 4; b++)
                #pragma unroll
                for (int d = 0; d < 4; d++) acc[a][b][d] = 0.f;

        // resolve this thread's 4 A-rows once per tile (rows r_ld + 32*i)
        const __half* asrc[4]; bool aval[4];
        #pragma unroll
        for (int i = 0; i < 4; i++) {
            int ar = tile * 128 + r_ld + i * 32;
            if (self) {
                aval[i] = (ar < n);
                asrc[i] = g_h1 + (size_t)(aval[i] ? ar : 0) * 256;
            } else {
                aval[i] = (ar < cnt);
                asrc[i] = g_h1 + (size_t)(aval[i] ? srcl[ar] : 0) * 256;
            }
        }

        auto issue = [&](int c) {
            if (c < 4) {
                int kc = c * 64;
                uint32_t sa = sbase + (uint32_t)(c % 3) * STAGE_BYTES;
                #pragma unroll
                for (int i = 0; i < 4; i++) {
                    int row = r_ld + i * 32;
                    uint32_t da = sa + (row * LDSROW + q_ld * 8) * 2;
                    cp16(da, asrc[i] + kc + q_ld * 8, aval[i]);
                    cp16(da + 18432, BW + row * 256 + kc + q_ld * 8, true);
                }
            }
            asm volatile("cp.async.commit_group;");
        };

        issue(0); issue(1);
        #pragma unroll 1
        for (int c = 0; c < 4; c++) {
            asm volatile("cp.async.wait_group 1;");
            __syncthreads();
            issue(c + 2);
            uint32_t As_u = sbase + (uint32_t)(c % 3) * STAGE_BYTES;
            uint32_t Bs_u = As_u + 18432;
            #pragma unroll
            for (int ks = 0; ks < 64; ks += 16) {
                uint32_t afr[4][4];
                #pragma unroll
                for (int mi = 0; mi < 4; mi++) {
                    int row = wm * 64 + mi * 16 + ((lane >> 3) & 1) * 8 + (lane & 7);
                    int kofs = ks + ((lane >> 4) << 3);
                    ldmx4(afr[mi], As_u + (row * LDSROW + kofs) * 2);
                }
                #pragma unroll
                for (int p = 0; p < 2; p++) {
                    uint32_t bb[4];
                    int row = wn * 32 + p * 16 + ((lane >> 4) << 3) + (lane & 7);
                    int kofs = ks + (((lane >> 3) & 1) << 3);
                    ldmx4(bb, Bs_u + (row * LDSROW + kofs) * 2);
                    #pragma unroll
                    for (int mi = 0; mi < 4; mi++) {
                        mma16816(acc[mi][2 * p],     afr[mi], bb);
                        mma16816(acc[mi][2 * p + 1], afr[mi], bb + 2);
                    }
                }
            }
        }
        __syncthreads();   // pipeline smem free for epilogue reuse

        if (!self) {
            #pragma unroll
            for (int mi = 0; mi < 4; mi++) {
                int rr = wm * 64 + mi * 16 + g;
                #pragma unroll
                for (int ni = 0; ni < 4; ni++) {
                    int col = nhalf * 128 + wn * 32 + ni * 8 + 2 * t;
                    int ra = tile * 128 + rr, rb = ra + 8;
                    if (ra < cnt)
                        red_v2(g_acc + (size_t)dstl[ra] * 256 + col,
                               acc[mi][ni][0], acc[mi][ni][1]);
                    if (rb < cnt)
                        red_v2(g_acc + (size_t)dstl[rb] * 256 + col,
                               acc[mi][ni][2], acc[mi][ni][3]);
                }
            }
        } else {
            // fused: add sparse acc (flagged rows), relu, pooled reduce
            float* tilebuf = (float*)dsm;                         // [128][66]
            int*   sbatch  = (int*)(dsm + 3 * STAGE_BYTES);
            if (tid < 128) {
                int r = tile * 128 + tid;
                sbatch[tid] = (r < n) ? bids[r] : -1;
            }
            #pragma unroll
            for (int h = 0; h < 2; h++) {
                __syncthreads();
                if ((wn >> 1) == h) {
                    #pragma unroll
                    for (int mi = 0; mi < 4; mi++) {
                        int rl0 = wm * 64 + mi * 16 + g;
                        #pragma unroll
                        for (int ni = 0; ni < 4; ni++) {
                            int cl = (wn & 1) * 32 + ni * 8 + 2 * t;   // 0..63
                            int gcol = nhalf * 128 + h * 64 + cl;
                            int ra = tile * 128 + rl0, rb = ra + 8;
                            float v0 = acc[mi][ni][0], v1 = acc[mi][ni][1];
                            float v2 = acc[mi][ni][2], v3 = acc[mi][ni][3];
                            if (ra < n && g_flag[ra]) {
                                float2 s = *(float2*)(g_acc + (size_t)ra * 256 + gcol);
                                v0 += s.x; v1 += s.y;
                            }
                            if (rb < n && g_flag[rb]) {
                                float2 s = *(float2*)(g_acc + (size_t)rb * 256 + gcol);
                                v2 += s.x; v3 += s.y;
                            }
                            tilebuf[rl0 * 66 + cl] = v0;
                            tilebuf[rl0 * 66 + cl + 1] = v1;
                            tilebuf[(rl0 + 8) * 66 + cl] = v2;
                            tilebuf[(rl0 + 8) * 66 + cl + 1] = v3;
                        }
                    }
                }
                __syncthreads();
                {
                    int col = tid & 63, q = tid >> 6;          // 4 row-groups x 64 cols
                    float sum = 0.f; int cur = -1;
                    #pragma unroll 8
                    for (int rr = q * 32; rr < q * 32 + 32; rr++) {
                        int b = sbatch[rr];
                        if (b != cur) {
                            if (cur >= 0)
                                atomicAdd(&out[cur * 256 + nhalf * 128 + h * 64 + col], sum);
                            sum = 0.f; cur = b;
                        }
                        if (b >= 0) {
                            float v = tilebuf[rr * 66 + col];
                            sum += (v > 0.f ? v : 0.f);
                        }
                    }
                    if (cur >= 0)
                        atomicAdd(&out[cur * 256 + nhalf * 128 + h * 64 + col], sum);
                }
            }
            __syncthreads();
        }
    }
}

// ---------------- counts + finalize ----------------
__global__ void count_kernel(const int* __restrict__ bids, int n) {
    __shared__ int loc[8];
    if (threadIdx.x < 8) loc[threadIdx.x] = 0;
    __syncthreads();
    for (int i = blockIdx.x * blockDim.x + threadIdx.x; i < n;
         i += gridDim.x * blockDim.x)
        atomicAdd(&loc[bids[i]], 1);
    __syncthreads();
    if (threadIdx.x < 8) atomicAdd(&g_counts[threadIdx.x], (float)loc[threadIdx.x]);
}

__global__ void finalize_kernel(float* out) {
    int e = blockIdx.x * 256 + threadIdx.x;
    if (e < 2048) out[e] = out[e] / g_counts[e >> 8];
}

// ---------------- launch ----------------
extern "C" void kernel_launch(void* const* d_in, const int* in_sizes, int n_in,
                              void* d_out, int out_size) {
    const float* feats = (const float*)d_in[0];
    const float* W1    = (const float*)d_in[1];
    const float* W2    = (const float*)d_in[2];
    const int*   nbr   = (const int*)d_in[3];
    const int*   bids  = (const int*)d_in[4];
    int n = in_sizes[0] / 3;
    float* out = (float*)d_out;

    static int cfg = 0;
    if (!cfg) {
        cudaFuncSetAttribute(gemm_kernel,
                             cudaFuncAttributeMaxDynamicSharedMemorySize, SMEM_DYN);
        cfg = 1;
    }

    int tiles = (n + 127) / 128;
    prep_kernel<<<64, 256>>>(out);
    convw2_kernel<<<dim3(8, 8, 9), dim3(32, 8)>>>(W2);
    layer1_kernel<<<2048, 256>>>(feats, W1, nbr, n);
    zero_rows_kernel<<<dim3(256, 8), 64>>>();
    gemm_kernel<<<dim3(40, 16), 256, SMEM_DYN>>>(n, 0, bids, out);   // 8 taps x 2 halves
    gemm_kernel<<<dim3(2, tiles), 256, SMEM_DYN>>>(n, 1, bids, out); // self + fused pool
    count_kernel<<<128, 256>>>(bids, n);
    finalize_kernel<<<8, 256>>>(out);
}